// round 2
// baseline (speedup 1.0000x reference)
#include <cuda_runtime.h>

#define HW    4096
#define CCH   64
#define NPAIR 28
#define PP    441

// Scratch (device globals: allocation-free per harness rules)
__device__ __align__(16) float g_cor[(size_t)NPAIR * PP * HW];  // ~202 MB
__device__ float g_mean[PP];
__device__ float g_rstd[PP];
__device__ __align__(16) float g_w2t[PP * 64];  // folded weights, [p][o]
__device__ float g_bias[64];

// Bank-conflict swizzle: fold word-index bit5 into bit1 (float2-safe, involution)
__device__ __forceinline__ int swz(int b) { return b ^ ((b >> 4) & 2); }

// ---------------------------------------------------------------------------
// Correlation inner body: 4 contiguous w x NQ contiguous q register tile.
// f2 smem index = w + 2q  (width pre-padded by 20 on each side, row width 104)
// ---------------------------------------------------------------------------
template <int NQ>
__device__ __forceinline__ void corr_body(const float* __restrict__ f1row,
                                          const float* __restrict__ f2row,
                                          int a0, int a1, const int* boff,
                                          float (&acc)[6][4]) {
#pragma unroll 8
    for (int c = 0; c < 64; ++c) {
        const float* F1 = f1row + c * 64;
        const float* F2 = f2row + c * 104;
        float2 x = *reinterpret_cast<const float2*>(F1 + a0);
        float2 y = *reinterpret_cast<const float2*>(F1 + a1);
        float a[4] = {x.x, x.y, y.x, y.y};
        float bb[2 * (NQ + 1)];
#pragma unroll
        for (int m = 0; m < NQ + 1; ++m) {
            float2 v = *reinterpret_cast<const float2*>(F2 + boff[m]);
            bb[2 * m]     = v.x;
            bb[2 * m + 1] = v.y;
        }
#pragma unroll
        for (int j = 0; j < NQ; ++j)
#pragma unroll
            for (int k = 0; k < 4; ++k)
                acc[j][k] = fmaf(a[k], bb[k + 2 * j], acc[j][k]);
    }
}

// ---------------------------------------------------------------------------
// Kernel 1: correlation volume. grid (32 h-pairs, 28 pairs), 128 threads.
// smem: f1 [2][64][64] + f2 padded row [2][64][104]  = 84 KB dynamic
// cor[n, p*21+q, h, w] = sum_c f1[c,h,w] * f2[c, h+2p-20, w+2q-20]
// ---------------------------------------------------------------------------
__global__ void __launch_bounds__(128) corr_kernel(const float* __restrict__ feats) {
    extern __shared__ float sm[];
    float* f1s = sm;                  // [2][64][64]
    float* f2s = sm + 2 * 64 * 64;    // [2][64][104]

    const int tid = threadIdx.x;
    const int n   = blockIdx.y;
    const int h0  = blockIdx.x * 2;
    const int b   = n / 7, t = n % 7;
    const float* f1f = feats + (size_t)(b * 8 + t) * CCH * HW;
    const float* f2f = f1f + (size_t)CCH * HW;  // next frame, same batch

    // stage f1 rows (swizzled columns)
    for (int idx = tid; idx < 2 * 64 * 64; idx += 128) {
        int hh = idx >> 12;
        int c  = (idx >> 6) & 63;
        int w  = idx & 63;
        f1s[((hh << 6) + c) * 64 + swz(w)] = f1f[c * HW + (h0 + hh) * 64 + w];
    }

    const int hh = tid >> 6;
    const int r6 = tid & 63;
    const int qg = r6 >> 4;
    const int wg = r6 & 15;
    const int qbase = (qg == 0) ? 0 : 5 * qg + 1;  // q groups: 6,5,5,5
    const float* f1row = f1s + hh * (64 * 64);
    const float* f2row = f2s + hh * (64 * 104);
    const int a0 = swz(wg * 4);
    const int a1 = swz(wg * 4 + 2);
    int boff[7];
#pragma unroll
    for (int m = 0; m < 7; ++m) boff[m] = swz(wg * 4 + 2 * qbase + 2 * m);

    for (int p = 0; p < 21; ++p) {
        const int dy = 2 * p - 20;
        __syncthreads();
        // stage padded f2 rows for this dy (zeros outside the frame)
        for (int idx = tid; idx < 2 * 64 * 104; idx += 128) {
            int hhh = idx / (64 * 104);
            int rem = idx - hhh * (64 * 104);
            int c   = rem / 104;
            int wp  = rem - c * 104;
            int r   = h0 + hhh + dy;
            int ww  = wp - 20;
            float v = 0.f;
            if (((unsigned)r < 64u) & ((unsigned)ww < 64u))
                v = f2f[c * HW + r * 64 + ww];
            f2s[(hhh * 64 + c) * 104 + swz(wp)] = v;
        }
        __syncthreads();

        float acc[6][4];
#pragma unroll
        for (int j = 0; j < 6; ++j)
#pragma unroll
            for (int k = 0; k < 4; ++k) acc[j][k] = 0.f;

        if (qg == 0) corr_body<6>(f1row, f2row, a0, a1, boff, acc);
        else         corr_body<5>(f1row, f2row, a0, a1, boff, acc);

        const int nq = (qg == 0) ? 6 : 5;
        float* outp = g_cor + ((size_t)n * PP + (size_t)(p * 21 + qbase)) * HW
                      + (h0 + hh) * 64 + wg * 4;
        for (int j = 0; j < nq; ++j) {
            float4 v = make_float4(acc[j][0], acc[j][1], acc[j][2], acc[j][3]);
            *reinterpret_cast<float4*>(outp + (size_t)j * HW) = v;
        }
    }
}

// ---------------------------------------------------------------------------
// Kernel 2: per-channel batch stats (mean, rstd) over N,H,W.  441 blocks.
// ---------------------------------------------------------------------------
__global__ void __launch_bounds__(256) stats_kernel() {
    const int p   = blockIdx.x;
    const int tid = threadIdx.x;
    float s = 0.f, ss = 0.f;
    for (int n = 0; n < NPAIR; ++n) {
        const float4* row =
            reinterpret_cast<const float4*>(g_cor + ((size_t)n * PP + p) * HW);
        for (int i = tid; i < HW / 4; i += 256) {
            float4 v = row[i];
            s  += v.x + v.y + v.z + v.w;
            ss += v.x * v.x + v.y * v.y + v.z * v.z + v.w * v.w;
        }
    }
    __shared__ float rs[256], rss[256];
    rs[tid] = s; rss[tid] = ss;
    __syncthreads();
    for (int ofs = 128; ofs > 0; ofs >>= 1) {
        if (tid < ofs) { rs[tid] += rs[tid + ofs]; rss[tid] += rss[tid + ofs]; }
        __syncthreads();
    }
    if (tid == 0) {
        const float inv = 1.f / (float)(NPAIR * HW);
        float mean = rs[0] * inv;
        float var  = rss[0] * inv - mean * mean;
        g_mean[p] = mean;
        g_rstd[p] = rsqrtf(var + 1e-5f);
    }
}

// ---------------------------------------------------------------------------
// Kernel 3: fold BN into conv weights.  W2T[p][o] = conv_w[o,p]*gamma_p*rstd_p
//           bias[o] = sum_p conv_w[o,p]*(beta_p - gamma_p*rstd_p*mean_p)
// ---------------------------------------------------------------------------
__global__ void __launch_bounds__(256) fold_kernel(const float* __restrict__ gamma,
                                                   const float* __restrict__ beta,
                                                   const float* __restrict__ convw) {
    __shared__ float sscale[PP], sshift[PP];
    const int tid = threadIdx.x;
    for (int p = tid; p < PP; p += 256) {
        float sc = gamma[p] * g_rstd[p];
        sscale[p] = sc;
        sshift[p] = beta[p] - sc * g_mean[p];
    }
    __syncthreads();
    for (int idx = tid; idx < PP * 64; idx += 256) {
        int p = idx >> 6, o = idx & 63;
        g_w2t[idx] = convw[o * PP + p] * sscale[p];
    }
    if (tid < 64) {
        float bsum = 0.f;
        for (int p = 0; p < PP; ++p) bsum += convw[tid * PP + p] * sshift[p];
        g_bias[tid] = bsum;
    }
}

// ---------------------------------------------------------------------------
// Kernel 4: 1x1 conv as GEMM  [128 pix x 64 out] tile, K=441 in chunks of 21.
// grid (32 pixel-tiles, 28 pairs), 256 threads, 4pix x 8out register tile.
// ---------------------------------------------------------------------------
__global__ void __launch_bounds__(256) conv_kernel(float* __restrict__ out) {
    __shared__ float As[21 * 128];
    __shared__ float Bs[21 * 64];
    const int tid     = threadIdx.x;
    const int n       = blockIdx.y;
    const int pixbase = blockIdx.x * 128;
    const int og      = tid >> 5;   // 8 output-channel group
    const int pxg     = tid & 31;   // 4-pixel group
    const float* corn = g_cor + (size_t)n * PP * HW;

    float acc[8][4];
#pragma unroll
    for (int s = 0; s < 8; ++s)
#pragma unroll
        for (int r = 0; r < 4; ++r) acc[s][r] = 0.f;

    for (int pc = 0; pc < 21; ++pc) {
        __syncthreads();
        for (int idx = tid; idx < 21 * 128; idx += 256) {
            int i = idx >> 7, jx = idx & 127;
            As[idx] = corn[(size_t)(pc * 21 + i) * HW + pixbase + jx];
        }
        for (int idx = tid; idx < 21 * 64; idx += 256)
            Bs[idx] = g_w2t[pc * 21 * 64 + idx];
        __syncthreads();
#pragma unroll
        for (int i = 0; i < 21; ++i) {
            float4 a   = *reinterpret_cast<const float4*>(&As[i * 128 + pxg * 4]);
            float4 b03 = *reinterpret_cast<const float4*>(&Bs[i * 64 + og * 8]);
            float4 b47 = *reinterpret_cast<const float4*>(&Bs[i * 64 + og * 8 + 4]);
            float bv[8] = {b03.x, b03.y, b03.z, b03.w, b47.x, b47.y, b47.z, b47.w};
            float av[4] = {a.x, a.y, a.z, a.w};
#pragma unroll
            for (int s = 0; s < 8; ++s)
#pragma unroll
                for (int r = 0; r < 4; ++r)
                    acc[s][r] = fmaf(bv[s], av[r], acc[s][r]);
        }
    }

    const int b = n / 7, t = n % 7;
    float* outn = out + (size_t)(b * 8 + t) * 64 * HW + pixbase + pxg * 4;
#pragma unroll
    for (int s = 0; s < 8; ++s) {
        int o = og * 8 + s;
        float bo = g_bias[o];
        float4 v = make_float4(acc[s][0] + bo, acc[s][1] + bo,
                               acc[s][2] + bo, acc[s][3] + bo);
        *reinterpret_cast<float4*>(outn + (size_t)o * HW) = v;
    }
}

// ---------------------------------------------------------------------------
// Kernel 5: zero the appended time frame (t = 7) for all batches.
// ---------------------------------------------------------------------------
__global__ void zero_tail_kernel(float* __restrict__ out) {
    int idx = blockIdx.x * 256 + threadIdx.x;   // 4*64*4096/4 = 262144 float4
    if (idx < 262144) {
        int b = idx >> 16;
        int r = idx & 65535;
        reinterpret_cast<float4*>(out)[(size_t)(b * 8 + 7) * 64 * 1024 + r] =
            make_float4(0.f, 0.f, 0.f, 0.f);
    }
}

// ---------------------------------------------------------------------------
extern "C" void kernel_launch(void* const* d_in, const int* in_sizes, int n_in,
                              void* d_out, int out_size) {
    const float* feats = (const float*)d_in[0];
    const float* gamma = (const float*)d_in[1];
    const float* beta  = (const float*)d_in[2];
    const float* convw = (const float*)d_in[3];
    float* out = (float*)d_out;

    const int corr_smem = (2 * 64 * 64 + 2 * 64 * 104) * 4;  // 86016 B
    cudaFuncSetAttribute(corr_kernel, cudaFuncAttributeMaxDynamicSharedMemorySize,
                         corr_smem);

    corr_kernel<<<dim3(32, 28), 128, corr_smem>>>(feats);
    stats_kernel<<<441, 256>>>();
    fold_kernel<<<1, 256>>>(gamma, beta, convw);
    conv_kernel<<<dim3(32, 28), 256>>>(out);
    zero_tail_kernel<<<1024, 256>>>(out);
}

// round 4
// speedup vs baseline: 1.6231x; 1.6231x over previous
#include <cuda_runtime.h>
#include <cstdint>

#define HW 4096
#define PP 441
#define NPAIR 28

typedef unsigned int u32;

__device__ __align__(16) float g_cor[(size_t)NPAIR * PP * HW];
__device__ float g_mean[PP];
__device__ float g_rstd[PP];
__device__ __align__(16) float g_w2t[PP * 64];
__device__ float g_bias[64];

__device__ __forceinline__ void cpa16(u32 dst, const void* src, bool v) {
    int sz = v ? 16 : 0;
    asm volatile("cp.async.cg.shared.global [%0], [%1], 16, %2;\n" :: "r"(dst), "l"(src), "r"(sz));
}
__device__ __forceinline__ void cpa_commit() { asm volatile("cp.async.commit_group;\n"); }
template <int N> __device__ __forceinline__ void cpa_wait() {
    asm volatile("cp.async.wait_group %0;\n" :: "n"(N));
}
// 16B-unit swizzle for conflict-free LDS.128
__device__ __forceinline__ int swzu(int u) { return u ^ ((u >> 3) & 1); }

// ---------------------------------------------------------------------------
// corr: grid (8 h-tiles, 3 p-thirds, 28 pairs), 128 thr. smem 90112 B.
// Buffer: f2 [8c][8r][112w] (valid units 5..20, border zero) + f1 [8c][8r][64w]
// Thread (qh=tid>>6, h=(tid>>3)&7, wg=tid&7): 8w x 11q tile, q = 10*qh + j.
// ---------------------------------------------------------------------------
#define F2CH 896
#define F1CH 512
#define F2SZ 7168
#define BUF  11264

__global__ void __launch_bounds__(128) corr_kernel(const float* __restrict__ feats) {
    extern __shared__ float sm[];
    const int tid = threadIdx.x;
    const int n = blockIdx.z, pr0 = blockIdx.y * 7, h0 = blockIdx.x * 8;
    const int bb = n / 7, tt = n % 7;
    const float* f1f = feats + (size_t)(bb * 8 + tt) * 64 * HW;
    const float* f2f = f1f + (size_t)64 * HW;
    const u32 smb = (u32)__cvta_generic_to_shared(sm);

    // zero f2 border units (both buffers)
    for (int idx = tid; idx < 1536; idx += 128) {
        int bf = idx / 768, rem = idx % 768;
        int c = rem / 96, r2 = rem % 96, r = r2 / 12, k = r2 % 12;
        int u = (k < 5) ? k : k + 16;
        float4* p = reinterpret_cast<float4*>(sm + bf * BUF + c * F2CH + r * 112) + swzu(u);
        *p = make_float4(0.f, 0.f, 0.f, 0.f);
    }

    const int qh = tid >> 6, h = (tid >> 3) & 7, wg = tid & 7;

    auto issue = [&](int s, int bf) {
        const int p = pr0 + (s >> 3), c0 = (s & 7) * 8, dy = 2 * p - 20;
        const u32 bbase = smb + (u32)(bf * BUF) * 4u;
#pragma unroll
        for (int i = 0; i < 8; ++i) {  // f2: 1024 units
            int idx = tid + i * 128;
            int c = idx >> 7, r = (idx >> 4) & 7, uu = idx & 15;
            int row = h0 + r + dy;
            bool v = (unsigned)row < 64u;
            int rc = v ? row : 0;
            cpa16(bbase + (u32)(c * F2CH + r * 112 + swzu(5 + uu) * 4) * 4u,
                  f2f + (size_t)(c0 + c) * HW + rc * 64 + uu * 4, v);
        }
#pragma unroll
        for (int i = 0; i < 8; ++i) {  // f1: 1024 units
            int idx = tid + i * 128;
            int c = idx >> 7, r = (idx >> 4) & 7, uu = idx & 15;
            cpa16(bbase + (u32)(F2SZ + c * F1CH + r * 64 + swzu(uu) * 4) * 4u,
                  f1f + (size_t)(c0 + c) * HW + (h0 + r) * 64 + uu * 4, true);
        }
        cpa_commit();
    };

    // per-thread smem word offsets
    int o1a = h * 64 + swzu(wg * 2) * 4;
    int o1b = h * 64 + swzu(wg * 2 + 1) * 4;
    int om[7];
#pragma unroll
    for (int m = 0; m < 7; ++m) om[m] = h * 112 + swzu(wg * 2 + 5 * qh + m) * 4;

    const int NS = 56;
    float acc[11][8];
    issue(0, 0);
    issue(1, 1);

    for (int s = 0; s < NS; ++s) {
        const int bf = s & 1, ck = s & 7;
        if (s == NS - 1) cpa_wait<0>(); else cpa_wait<1>();
        __syncthreads();
        if (ck == 0) {
#pragma unroll
            for (int j = 0; j < 11; ++j)
#pragma unroll
                for (int k = 0; k < 8; ++k) acc[j][k] = 0.f;
        }
        const float* f1b = sm + bf * BUF + F2SZ;
        const float* f2b = sm + bf * BUF;
#pragma unroll 4
        for (int c = 0; c < 8; ++c) {
            float4 x = *reinterpret_cast<const float4*>(f1b + c * F1CH + o1a);
            float4 y = *reinterpret_cast<const float4*>(f1b + c * F1CH + o1b);
            float a[8] = {x.x, x.y, x.z, x.w, y.x, y.y, y.z, y.w};
            float bv[28];
#pragma unroll
            for (int m = 0; m < 7; ++m) {
                float4 t = *reinterpret_cast<const float4*>(f2b + c * F2CH + om[m]);
                bv[4*m] = t.x; bv[4*m+1] = t.y; bv[4*m+2] = t.z; bv[4*m+3] = t.w;
            }
#pragma unroll
            for (int j = 0; j < 11; ++j)
#pragma unroll
                for (int k = 0; k < 8; ++k)
                    acc[j][k] = fmaf(a[k], bv[2 * j + k], acc[j][k]);
        }
        __syncthreads();
        if (s + 2 < NS) issue(s + 2, bf);
        if (ck == 7) {
            const int p = pr0 + (s >> 3);
            float* outp = g_cor + ((size_t)n * PP + (size_t)(p * 21 + 10 * qh)) * HW
                          + (h0 + h) * 64 + wg * 8;
            for (int j = (qh ? 1 : 0); j < 11; ++j) {
                float4 v0 = make_float4(acc[j][0], acc[j][1], acc[j][2], acc[j][3]);
                float4 v1 = make_float4(acc[j][4], acc[j][5], acc[j][6], acc[j][7]);
                *reinterpret_cast<float4*>(outp + (size_t)j * HW)     = v0;
                *reinterpret_cast<float4*>(outp + (size_t)j * HW + 4) = v1;
            }
        }
    }
}

// ---------------------------------------------------------------------------
__global__ void __launch_bounds__(256) stats_kernel() {
    const int p = blockIdx.x, tid = threadIdx.x;
    float s = 0.f, ss = 0.f;
    for (int n = 0; n < NPAIR; ++n) {
        const float4* row = reinterpret_cast<const float4*>(g_cor + ((size_t)n * PP + p) * HW);
        for (int i = tid; i < HW / 4; i += 256) {
            float4 v = row[i];
            s  += v.x + v.y + v.z + v.w;
            ss += v.x * v.x + v.y * v.y + v.z * v.z + v.w * v.w;
        }
    }
    __shared__ float rs[256], rss[256];
    rs[tid] = s; rss[tid] = ss;
    __syncthreads();
    for (int o = 128; o > 0; o >>= 1) {
        if (tid < o) { rs[tid] += rs[tid + o]; rss[tid] += rss[tid + o]; }
        __syncthreads();
    }
    if (tid == 0) {
        const float inv = 1.f / (float)(NPAIR * HW);
        float mean = rs[0] * inv;
        g_mean[p] = mean;
        g_rstd[p] = rsqrtf(rss[0] * inv - mean * mean + 1e-5f);
    }
}

// ---------------------------------------------------------------------------
__global__ void __launch_bounds__(256) fold_kernel(const float* __restrict__ gamma,
                                                   const float* __restrict__ beta,
                                                   const float* __restrict__ convw) {
    __shared__ float ssc[PP], ssh[PP];
    const int tid = threadIdx.x;
    for (int p = tid; p < PP; p += 256) {
        float sc = gamma[p] * g_rstd[p];
        ssc[p] = sc;
        ssh[p] = beta[p] - sc * g_mean[p];
    }
    __syncthreads();
    for (int idx = tid; idx < PP * 64; idx += 256) {
        int p = idx >> 6, o = idx & 63;
        g_w2t[idx] = convw[o * PP + p] * ssc[p];
    }
    if (tid < 64) {
        float bs = 0.f;
        for (int p = 0; p < PP; ++p) bs += convw[tid * PP + p] * ssh[p];
        g_bias[tid] = bs;
    }
}

// ---------------------------------------------------------------------------
// conv: grid (64 px-tiles, 28), 128 thr. 64px x 64out, K=441 in 21-chunks,
// double-buffered cp.async. Thread: og=tid>>4 (8 out), pxg=tid&15 (4 px).
// ---------------------------------------------------------------------------
__global__ void __launch_bounds__(128) conv_kernel(float* __restrict__ out) {
    __shared__ float As[2][21 * 64];
    __shared__ float Bs[2][21 * 64];
    const int tid = threadIdx.x, n = blockIdx.y, px0 = blockIdx.x * 64;
    const int og = tid >> 4, pxg = tid & 15;
    const float* corn = g_cor + (size_t)n * PP * HW;
    const u32 sa = (u32)__cvta_generic_to_shared(As);
    const u32 sb = (u32)__cvta_generic_to_shared(Bs);

    auto issue = [&](int pc, int bf) {
#pragma unroll
        for (int i = 0; i < 6; ++i) {
            int idx = tid + i * 128;
            if (idx < 672) {
                int half = idx >= 336;
                int id2 = half ? idx - 336 : idx;
                int c = id2 >> 4, u = id2 & 15;
                if (!half)
                    cpa16(sa + (u32)(bf * 1344 + c * 64 + u * 4) * 4u,
                          corn + (size_t)(pc * 21 + c) * HW + px0 + u * 4, true);
                else
                    cpa16(sb + (u32)(bf * 1344 + c * 64 + u * 4) * 4u,
                          g_w2t + (pc * 21 + c) * 64 + u * 4, true);
            }
        }
        cpa_commit();
    };

    float acc[8][4];
#pragma unroll
    for (int s = 0; s < 8; ++s)
#pragma unroll
        for (int r = 0; r < 4; ++r) acc[s][r] = 0.f;

    issue(0, 0);
    issue(1, 1);
    for (int pc = 0; pc < 21; ++pc) {
        const int bf = pc & 1;
        if (pc == 20) cpa_wait<0>(); else cpa_wait<1>();
        __syncthreads();
#pragma unroll
        for (int i = 0; i < 21; ++i) {
            float4 a  = *reinterpret_cast<const float4*>(&As[bf][i * 64 + pxg * 4]);
            float4 b0 = *reinterpret_cast<const float4*>(&Bs[bf][i * 64 + og * 8]);
            float4 b1 = *reinterpret_cast<const float4*>(&Bs[bf][i * 64 + og * 8 + 4]);
            float bv[8] = {b0.x, b0.y, b0.z, b0.w, b1.x, b1.y, b1.z, b1.w};
            float av[4] = {a.x, a.y, a.z, a.w};
#pragma unroll
            for (int s = 0; s < 8; ++s)
#pragma unroll
                for (int r = 0; r < 4; ++r)
                    acc[s][r] = fmaf(bv[s], av[r], acc[s][r]);
        }
        __syncthreads();
        if (pc + 2 < 21) issue(pc + 2, bf);
    }

    const int b = n / 7, t = n % 7;
    float* outn = out + (size_t)(b * 8 + t) * 64 * HW + px0 + pxg * 4;
#pragma unroll
    for (int s = 0; s < 8; ++s) {
        float bo = g_bias[og * 8 + s];
        float4 v = make_float4(acc[s][0] + bo, acc[s][1] + bo, acc[s][2] + bo, acc[s][3] + bo);
        *reinterpret_cast<float4*>(outn + (size_t)(og * 8 + s) * HW) = v;
    }
}

// ---------------------------------------------------------------------------
__global__ void zero_tail_kernel(float* __restrict__ out) {
    int idx = blockIdx.x * 256 + threadIdx.x;
    if (idx < 262144) {
        int b = idx >> 16, r = idx & 65535;
        reinterpret_cast<float4*>(out)[(size_t)(b * 8 + 7) * 64 * 1024 + r] =
            make_float4(0.f, 0.f, 0.f, 0.f);
    }
}

// ---------------------------------------------------------------------------
extern "C" void kernel_launch(void* const* d_in, const int* in_sizes, int n_in,
                              void* d_out, int out_size) {
    const float* feats = (const float*)d_in[0];
    const float* gamma = (const float*)d_in[1];
    const float* beta  = (const float*)d_in[2];
    const float* convw = (const float*)d_in[3];
    float* out = (float*)d_out;

    const int corr_smem = 2 * BUF * 4;  // 90112 B
    cudaFuncSetAttribute(corr_kernel, cudaFuncAttributeMaxDynamicSharedMemorySize, corr_smem);

    corr_kernel<<<dim3(8, 3, 28), 128, corr_smem>>>(feats);
    stats_kernel<<<441, 256>>>();
    fold_kernel<<<1, 256>>>(gamma, beta, convw);
    conv_kernel<<<dim3(64, 28), 128>>>(out);
    zero_tail_kernel<<<1024, 256>>>(out);
}

// round 5
// speedup vs baseline: 1.9387x; 1.1945x over previous
#include <cuda_runtime.h>
#include <cstdint>

#define HW 4096
#define PP 441
#define NPAIR 28

typedef unsigned int u32;
typedef unsigned long long ull;

__device__ __align__(16) float g_cor[(size_t)NPAIR * PP * HW];
__device__ float g_mean[PP];
__device__ float g_rstd[PP];
__device__ __align__(16) float g_w2t[PP * 64];
__device__ float g_bias[64];

__device__ __forceinline__ void cpa16(u32 dst, const void* src, bool v) {
    int sz = v ? 16 : 0;
    asm volatile("cp.async.cg.shared.global [%0], [%1], 16, %2;\n" :: "r"(dst), "l"(src), "r"(sz));
}
__device__ __forceinline__ void cpa_commit() { asm volatile("cp.async.commit_group;\n"); }
template <int N> __device__ __forceinline__ void cpa_wait() {
    asm volatile("cp.async.wait_group %0;\n" :: "n"(N));
}
// packed dual-fp32 FMA (sm_10x)
__device__ __forceinline__ void fma2(ull& d, ull a, ull b) {
    asm("fma.rn.f32x2 %0, %1, %2, %0;" : "+l"(d) : "l"(a), "l"(b));
}
__device__ __forceinline__ ull dup2(float x) {
    ull d; u32 xi = __float_as_uint(x);
    asm("mov.b64 %0, {%1, %1};" : "=l"(d) : "r"(xi));
    return d;
}
__device__ __forceinline__ void unpk(float& lo, float& hi, ull v) {
    asm("mov.b64 {%0, %1}, %2;" : "=f"(lo), "=f"(hi) : "l"(v));
}
// 16B-unit swizzle for conflict-free LDS.128
__device__ __forceinline__ int swzu(int u) { return u ^ ((u >> 3) & 1); }

// ---------------------------------------------------------------------------
// corr: grid (8 h-tiles, 3 p-thirds, 28 pairs), 128 thr. smem 90112 B.
// Buffer: f2 [8c][8r][112w] (valid units 5..20, border zero) + f1 [8c][8r][64w]
// Thread (qh=tid>>6, h=(tid>>3)&7, wg=tid&7): 8w x 11q tile, q = 10*qh + j.
// acc packed as f32x2 over w-pairs: acc2[j][k2] = (w0+2k2, w0+2k2+1).
// ---------------------------------------------------------------------------
#define F2CH 896
#define F1CH 512
#define F2SZ 7168
#define BUF  11264

__global__ void __launch_bounds__(128) corr_kernel(const float* __restrict__ feats) {
    extern __shared__ float sm[];
    const int tid = threadIdx.x;
    const int n = blockIdx.z, pr0 = blockIdx.y * 7, h0 = blockIdx.x * 8;
    const int bb = n / 7, tt = n % 7;
    const float* f1f = feats + (size_t)(bb * 8 + tt) * 64 * HW;
    const float* f2f = f1f + (size_t)64 * HW;
    const u32 smb = (u32)__cvta_generic_to_shared(sm);

    // zero f2 border units (both buffers)
    for (int idx = tid; idx < 1536; idx += 128) {
        int bf = idx / 768, rem = idx % 768;
        int c = rem / 96, r2 = rem % 96, r = r2 / 12, k = r2 % 12;
        int u = (k < 5) ? k : k + 16;
        float4* p = reinterpret_cast<float4*>(sm + bf * BUF + c * F2CH + r * 112) + swzu(u);
        *p = make_float4(0.f, 0.f, 0.f, 0.f);
    }

    const int qh = tid >> 6, h = (tid >> 3) & 7, wg = tid & 7;

    auto issue = [&](int s, int bf) {
        const int p = pr0 + (s >> 3), c0 = (s & 7) * 8, dy = 2 * p - 20;
        const u32 bbase = smb + (u32)(bf * BUF) * 4u;
#pragma unroll
        for (int i = 0; i < 8; ++i) {  // f2: 1024 units
            int idx = tid + i * 128;
            int c = idx >> 7, r = (idx >> 4) & 7, uu = idx & 15;
            int row = h0 + r + dy;
            bool v = (unsigned)row < 64u;
            int rc = v ? row : 0;
            cpa16(bbase + (u32)(c * F2CH + r * 112 + swzu(5 + uu) * 4) * 4u,
                  f2f + (size_t)(c0 + c) * HW + rc * 64 + uu * 4, v);
        }
#pragma unroll
        for (int i = 0; i < 8; ++i) {  // f1: 1024 units
            int idx = tid + i * 128;
            int c = idx >> 7, r = (idx >> 4) & 7, uu = idx & 15;
            cpa16(bbase + (u32)(F2SZ + c * F1CH + r * 64 + swzu(uu) * 4) * 4u,
                  f1f + (size_t)(c0 + c) * HW + (h0 + r) * 64 + uu * 4, true);
        }
        cpa_commit();
    };

    // per-thread smem word offsets
    const int o1a = h * 64 + swzu(wg * 2) * 4;
    const int o1b = h * 64 + swzu(wg * 2 + 1) * 4;
    int om[7];
#pragma unroll
    for (int m = 0; m < 7; ++m) om[m] = h * 112 + swzu(wg * 2 + 5 * qh + m) * 4;

    const int NS = 56;
    ull acc2[11][4];
    issue(0, 0);
    issue(1, 1);

    for (int s = 0; s < NS; ++s) {
        const int bf = s & 1, ck = s & 7;
        if (s == NS - 1) cpa_wait<0>(); else cpa_wait<1>();
        __syncthreads();
        if (ck == 0) {
#pragma unroll
            for (int j = 0; j < 11; ++j)
#pragma unroll
                for (int k2 = 0; k2 < 4; ++k2) acc2[j][k2] = 0ull;
        }
        const float* f1b = sm + bf * BUF + F2SZ;
        const float* f2b = sm + bf * BUF;
#pragma unroll 2
        for (int c = 0; c < 8; ++c) {
            ulonglong2 xa = *reinterpret_cast<const ulonglong2*>(f1b + c * F1CH + o1a);
            ulonglong2 xb = *reinterpret_cast<const ulonglong2*>(f1b + c * F1CH + o1b);
            ull a2[4] = {xa.x, xa.y, xb.x, xb.y};
#pragma unroll
            for (int m = 0; m < 7; ++m) {
                ulonglong2 t = *reinterpret_cast<const ulonglong2*>(f2b + c * F2CH + om[m]);
#pragma unroll
                for (int k2 = 0; k2 < 4; ++k2) {
                    const int j0 = 2 * m - k2;
                    const int j1 = 2 * m + 1 - k2;
                    if (j0 >= 0 && j0 <= 10) fma2(acc2[j0][k2], a2[k2], t.x);
                    if (j1 >= 0 && j1 <= 10) fma2(acc2[j1][k2], a2[k2], t.y);
                }
            }
        }
        __syncthreads();
        if (s + 2 < NS) issue(s + 2, bf);
        if (ck == 7) {
            const int p = pr0 + (s >> 3);
            float* outp = g_cor + ((size_t)n * PP + (size_t)(p * 21 + 10 * qh)) * HW
                          + (h0 + h) * 64 + wg * 8;
            for (int j = (qh ? 1 : 0); j < 11; ++j) {
                ulonglong2 v0, v1;
                v0.x = acc2[j][0]; v0.y = acc2[j][1];
                v1.x = acc2[j][2]; v1.y = acc2[j][3];
                *reinterpret_cast<ulonglong2*>(outp + (size_t)j * HW)     = v0;
                *reinterpret_cast<ulonglong2*>(outp + (size_t)j * HW + 4) = v1;
            }
        }
    }
}

// ---------------------------------------------------------------------------
__global__ void __launch_bounds__(256) stats_kernel() {
    const int p = blockIdx.x, tid = threadIdx.x;
    float s = 0.f, ss = 0.f;
    for (int n = 0; n < NPAIR; ++n) {
        const float4* row = reinterpret_cast<const float4*>(g_cor + ((size_t)n * PP + p) * HW);
        for (int i = tid; i < HW / 4; i += 256) {
            float4 v = row[i];
            s  += v.x + v.y + v.z + v.w;
            ss += v.x * v.x + v.y * v.y + v.z * v.z + v.w * v.w;
        }
    }
    __shared__ float rs[256], rss[256];
    rs[tid] = s; rss[tid] = ss;
    __syncthreads();
    for (int o = 128; o > 0; o >>= 1) {
        if (tid < o) { rs[tid] += rs[tid + o]; rss[tid] += rss[tid + o]; }
        __syncthreads();
    }
    if (tid == 0) {
        const float inv = 1.f / (float)(NPAIR * HW);
        float mean = rs[0] * inv;
        g_mean[p] = mean;
        g_rstd[p] = rsqrtf(rss[0] * inv - mean * mean + 1e-5f);
    }
}

// ---------------------------------------------------------------------------
__global__ void __launch_bounds__(256) fold_kernel(const float* __restrict__ gamma,
                                                   const float* __restrict__ beta,
                                                   const float* __restrict__ convw) {
    __shared__ float ssc[PP], ssh[PP];
    const int tid = threadIdx.x;
    for (int p = tid; p < PP; p += 256) {
        float sc = gamma[p] * g_rstd[p];
        ssc[p] = sc;
        ssh[p] = beta[p] - sc * g_mean[p];
    }
    __syncthreads();
    for (int idx = tid; idx < PP * 64; idx += 256) {
        int p = idx >> 6, o = idx & 63;
        g_w2t[idx] = convw[o * PP + p] * ssc[p];
    }
    if (tid < 64) {
        float bs = 0.f;
        for (int p = 0; p < PP; ++p) bs += convw[tid * PP + p] * ssh[p];
        g_bias[tid] = bs;
    }
}

// ---------------------------------------------------------------------------
// conv: grid (64 px-tiles, 28), 128 thr. 64px x 64out, K=441 in 21-chunks,
// double-buffered cp.async. Thread: og=tid>>4 (8 out), pxg=tid&15 (4 px).
// f32x2: acc2[s2][r] = output-channel pair (og*8+2*s2, +1) at pixel pxg*4+r.
// ---------------------------------------------------------------------------
__global__ void __launch_bounds__(128) conv_kernel(float* __restrict__ out) {
    __shared__ float As[2][21 * 64];
    __shared__ float Bs[2][21 * 64];
    const int tid = threadIdx.x, n = blockIdx.y, px0 = blockIdx.x * 64;
    const int og = tid >> 4, pxg = tid & 15;
    const float* corn = g_cor + (size_t)n * PP * HW;
    const u32 sa = (u32)__cvta_generic_to_shared(As);
    const u32 sb = (u32)__cvta_generic_to_shared(Bs);

    auto issue = [&](int pc, int bf) {
#pragma unroll
        for (int i = 0; i < 6; ++i) {
            int idx = tid + i * 128;
            if (idx < 672) {
                int half = idx >= 336;
                int id2 = half ? idx - 336 : idx;
                int c = id2 >> 4, u = id2 & 15;
                if (!half)
                    cpa16(sa + (u32)(bf * 1344 + c * 64 + u * 4) * 4u,
                          corn + (size_t)(pc * 21 + c) * HW + px0 + u * 4, true);
                else
                    cpa16(sb + (u32)(bf * 1344 + c * 64 + u * 4) * 4u,
                          g_w2t + (pc * 21 + c) * 64 + u * 4, true);
            }
        }
        cpa_commit();
    };

    ull acc2[4][4];
#pragma unroll
    for (int s2 = 0; s2 < 4; ++s2)
#pragma unroll
        for (int r = 0; r < 4; ++r) acc2[s2][r] = 0ull;

    issue(0, 0);
    issue(1, 1);
    for (int pc = 0; pc < 21; ++pc) {
        const int bf = pc & 1;
        if (pc == 20) cpa_wait<0>(); else cpa_wait<1>();
        __syncthreads();
#pragma unroll
        for (int i = 0; i < 21; ++i) {
            float4 a = *reinterpret_cast<const float4*>(&As[bf][i * 64 + pxg * 4]);
            ulonglong2 b01 = *reinterpret_cast<const ulonglong2*>(&Bs[bf][i * 64 + og * 8]);
            ulonglong2 b23 = *reinterpret_cast<const ulonglong2*>(&Bs[bf][i * 64 + og * 8 + 4]);
            ull b2[4] = {b01.x, b01.y, b23.x, b23.y};
            ull avd[4] = {dup2(a.x), dup2(a.y), dup2(a.z), dup2(a.w)};
#pragma unroll
            for (int s2 = 0; s2 < 4; ++s2)
#pragma unroll
                for (int r = 0; r < 4; ++r)
                    fma2(acc2[s2][r], avd[r], b2[s2]);
        }
        __syncthreads();
        if (pc + 2 < 21) issue(pc + 2, bf);
    }

    const int b = n / 7, t = n % 7;
    float* outn = out + (size_t)(b * 8 + t) * 64 * HW + px0 + pxg * 4;
#pragma unroll
    for (int s2 = 0; s2 < 4; ++s2) {
        float lo[4], hi[4];
#pragma unroll
        for (int r = 0; r < 4; ++r) unpk(lo[r], hi[r], acc2[s2][r]);
        const float bo0 = g_bias[og * 8 + 2 * s2];
        const float bo1 = g_bias[og * 8 + 2 * s2 + 1];
        float4 v0 = make_float4(lo[0] + bo0, lo[1] + bo0, lo[2] + bo0, lo[3] + bo0);
        float4 v1 = make_float4(hi[0] + bo1, hi[1] + bo1, hi[2] + bo1, hi[3] + bo1);
        *reinterpret_cast<float4*>(outn + (size_t)(og * 8 + 2 * s2) * HW)     = v0;
        *reinterpret_cast<float4*>(outn + (size_t)(og * 8 + 2 * s2 + 1) * HW) = v1;
    }
}

// ---------------------------------------------------------------------------
__global__ void zero_tail_kernel(float* __restrict__ out) {
    int idx = blockIdx.x * 256 + threadIdx.x;
    if (idx < 262144) {
        int b = idx >> 16, r = idx & 65535;
        reinterpret_cast<float4*>(out)[(size_t)(b * 8 + 7) * 64 * 1024 + r] =
            make_float4(0.f, 0.f, 0.f, 0.f);
    }
}

// ---------------------------------------------------------------------------
extern "C" void kernel_launch(void* const* d_in, const int* in_sizes, int n_in,
                              void* d_out, int out_size) {
    const float* feats = (const float*)d_in[0];
    const float* gamma = (const float*)d_in[1];
    const float* beta  = (const float*)d_in[2];
    const float* convw = (const float*)d_in[3];
    float* out = (float*)d_out;

    const int corr_smem = 2 * BUF * 4;  // 90112 B
    cudaFuncSetAttribute(corr_kernel, cudaFuncAttributeMaxDynamicSharedMemorySize, corr_smem);

    corr_kernel<<<dim3(8, 3, 28), 128, corr_smem>>>(feats);
    stats_kernel<<<441, 256>>>();
    fold_kernel<<<1, 256>>>(gamma, beta, convw);
    conv_kernel<<<dim3(64, 28), 128>>>(out);
    zero_tail_kernel<<<1024, 256>>>(out);
}